// round 8
// baseline (speedup 1.0000x reference)
#include <cuda_runtime.h>

#define BB 2
#define SS 512
#define DD 256
#define BS (BB*SS)
#define NT 16            // 512/32 j-tiles per dim
#define NP 136           // NT*(NT+1)/2 triangular tile pairs

// Scratch (allocation-free rule: __device__ globals).
__device__ float g_WT[DD*DD];     // W transposed: [k][e] = W[e][k]
__device__ float g_ET[BB*DD*SS];  // E transposed: [b][e][j] = exp(2*P[b][j][e])
__device__ float g_R [BS*DD];     // R row-major:  [r][e]    = exp(-2*P[r][e])
__device__ float g_S [BS*SS];     // raw scores   [r][j]

__device__ __forceinline__ float frcp_approx(float x){
    float r; asm("rcp.approx.f32 %0, %1;" : "=f"(r) : "f"(x)); return r;
}

// K0: WT[k][e] = W[e][k].  Grid 64 (8x8 tiles of 32x32), block 256 (32x8).
__global__ void __launch_bounds__(256) k0_wt(const float* __restrict__ W){
    __shared__ float t[32][33];
    const int bx = blockIdx.x & 7, by = blockIdx.x >> 3;
    const int lx = threadIdx.x & 31, ly = threadIdx.x >> 5;  // ly 0..7
    #pragma unroll
    for (int r = 0; r < 4; r++)
        t[ly + 8*r][lx] = W[(by*32 + ly + 8*r) * DD + bx*32 + lx];
    __syncthreads();
    #pragma unroll
    for (int r = 0; r < 4; r++)
        g_WT[(bx*32 + ly + 8*r) * DD + by*32 + lx] = t[lx][ly + 8*r];
}

// K1: P = Q @ Wm^T via WT (coalesced L2 reads, no W staging).
// i-tile = 8, grid 128. Thread e owns output column e.
__global__ void __launch_bounds__(256) k1_proj(const float* __restrict__ Q){
    __shared__ __align__(16) float sQT[DD][8];   // [k][m], 8 KB
    const int tid = threadIdx.x;
    const int r0  = blockIdx.x * 8;

    #pragma unroll
    for (int m = 0; m < 8; m++) sQT[tid][m] = Q[(r0 + m) * DD + tid];
    __syncthreads();

    float acc[8] = {0,0,0,0,0,0,0,0};
    const float* wt = g_WT + tid;
    #pragma unroll 8
    for (int k = 0; k < DD; k++) {
        float wv = __ldg(wt + k * DD);
        float4 q0 = *(const float4*)&sQT[k][0];
        float4 q1 = *(const float4*)&sQT[k][4];
        acc[0] = fmaf(wv, q0.x, acc[0]); acc[1] = fmaf(wv, q0.y, acc[1]);
        acc[2] = fmaf(wv, q0.z, acc[2]); acc[3] = fmaf(wv, q0.w, acc[3]);
        acc[4] = fmaf(wv, q1.x, acc[4]); acc[5] = fmaf(wv, q1.y, acc[5]);
        acc[6] = fmaf(wv, q1.z, acc[6]); acc[7] = fmaf(wv, q1.w, acc[7]);
    }

    const float C2 = 2.885390081777927f; // 2*log2(e)
    const int b  = r0 / SS;
    const int jr = r0 % SS;
    #pragma unroll
    for (int m = 0; m < 8; m++) {
        float p = acc[m];
        g_ET[(size_t)b * DD * SS + (size_t)tid * SS + (jr + m)] = exp2f( C2 * p);
        g_R [(size_t)(r0 + m) * DD + tid]                       = exp2f(-C2 * p);
    }
}

// K2s: scores for one 32x32 tile pair (ti<=tj) via antisymmetry.
// Block 256 = 2 e-groups x 128; thread = (i, 2 j-float4). Writes direct tile
// and (if off-diagonal) negated transpose.
__global__ void __launch_bounds__(256) k2_scores(const float* __restrict__ vm){
    __shared__ __align__(16) float sR[32][260];   // R tile; reused after e-loop
    __shared__ float sm2[256];
    __shared__ float s_red[8];

    const int tid  = threadIdx.x;
    const int lane = tid & 31;
    const int w    = tid >> 5;
    const int b    = blockIdx.x / NP;
    int p = blockIdx.x - b * NP;
    int ti = 0;
    while (p >= NT - ti) { p -= NT - ti; ti++; }
    const int tj = ti + p;
    const int I = ti * 32, J = tj * 32;

    // vm staging + sum(vm)
    {
        float vme = vm[tid];
        sm2[tid] = -2.f * vme;
        float svp = vme;
        #pragma unroll
        for (int off = 16; off; off >>= 1) svp += __shfl_xor_sync(0xffffffffu, svp, off);
        if (lane == 0) s_red[w] = svp;
    }
    // R tile staging (2048 float4, coalesced)
    {
        const float4* R4 = (const float4*)(g_R + (size_t)(b * SS + I) * DD);
        #pragma unroll
        for (int k = 0; k < 8; k++) {
            int lin = k * 256 + tid;
            int row = lin >> 6;
            int c4  = lin & 63;
            float4 v = R4[row * 64 + c4];
            *(float4*)&sR[row][c4 * 4] = v;
        }
    }
    __syncthreads();
    const float sv = s_red[0] + s_red[1] + s_red[2] + s_red[3] +
                     s_red[4] + s_red[5] + s_red[6] + s_red[7];

    const int grp  = tid >> 7;
    const int t    = tid & 127;
    const int i    = t >> 2;
    const int col0 = tj * 8 + (t & 3) * 2;

    float4 acc0 = {0,0,0,0}, acc1 = {0,0,0,0};
    {
        const float4* EB = (const float4*)(g_ET + (size_t)b * DD * SS);
        const int e0 = grp * 128;
        const float4* pe = EB + (size_t)e0 * (SS/4) + col0;
        float4 n0 = pe[0],   n1 = pe[1];
        float4 n2 = pe[128], n3 = pe[129];
        float4 n4 = pe[256], n5 = pe[257];
        float4 n6 = pe[384], n7 = pe[385];
        pe += 512;

        for (int chunk = 0; chunk < 32; chunk++) {
            float4 c0=n0,c1=n1,c2=n2,c3=n3,c4=n4,c5=n5,c6=n6,c7=n7;
            if (chunk < 31) {
                n0=pe[0];   n1=pe[1];
                n2=pe[128]; n3=pe[129];
                n4=pe[256]; n5=pe[257];
                n6=pe[384]; n7=pe[385];
                pe += 512;
            }
            const int e = e0 + chunk * 4;
            float4 r4 = *(const float4*)&sR[i][e];
            float4 m4 = *(const float4*)&sm2[e];

            acc0.x = fmaf(m4.x, frcp_approx(fmaf(c0.x, r4.x, 1.f)), acc0.x);
            acc0.y = fmaf(m4.x, frcp_approx(fmaf(c0.y, r4.x, 1.f)), acc0.y);
            acc0.z = fmaf(m4.x, frcp_approx(fmaf(c0.z, r4.x, 1.f)), acc0.z);
            acc0.w = fmaf(m4.x, frcp_approx(fmaf(c0.w, r4.x, 1.f)), acc0.w);
            acc1.x = fmaf(m4.x, frcp_approx(fmaf(c1.x, r4.x, 1.f)), acc1.x);
            acc1.y = fmaf(m4.x, frcp_approx(fmaf(c1.y, r4.x, 1.f)), acc1.y);
            acc1.z = fmaf(m4.x, frcp_approx(fmaf(c1.z, r4.x, 1.f)), acc1.z);
            acc1.w = fmaf(m4.x, frcp_approx(fmaf(c1.w, r4.x, 1.f)), acc1.w);

            acc0.x = fmaf(m4.y, frcp_approx(fmaf(c2.x, r4.y, 1.f)), acc0.x);
            acc0.y = fmaf(m4.y, frcp_approx(fmaf(c2.y, r4.y, 1.f)), acc0.y);
            acc0.z = fmaf(m4.y, frcp_approx(fmaf(c2.z, r4.y, 1.f)), acc0.z);
            acc0.w = fmaf(m4.y, frcp_approx(fmaf(c2.w, r4.y, 1.f)), acc0.w);
            acc1.x = fmaf(m4.y, frcp_approx(fmaf(c3.x, r4.y, 1.f)), acc1.x);
            acc1.y = fmaf(m4.y, frcp_approx(fmaf(c3.y, r4.y, 1.f)), acc1.y);
            acc1.z = fmaf(m4.y, frcp_approx(fmaf(c3.z, r4.y, 1.f)), acc1.z);
            acc1.w = fmaf(m4.y, frcp_approx(fmaf(c3.w, r4.y, 1.f)), acc1.w);

            acc0.x = fmaf(m4.z, frcp_approx(fmaf(c4.x, r4.z, 1.f)), acc0.x);
            acc0.y = fmaf(m4.z, frcp_approx(fmaf(c4.y, r4.z, 1.f)), acc0.y);
            acc0.z = fmaf(m4.z, frcp_approx(fmaf(c4.z, r4.z, 1.f)), acc0.z);
            acc0.w = fmaf(m4.z, frcp_approx(fmaf(c4.w, r4.z, 1.f)), acc0.w);
            acc1.x = fmaf(m4.z, frcp_approx(fmaf(c5.x, r4.z, 1.f)), acc1.x);
            acc1.y = fmaf(m4.z, frcp_approx(fmaf(c5.y, r4.z, 1.f)), acc1.y);
            acc1.z = fmaf(m4.z, frcp_approx(fmaf(c5.z, r4.z, 1.f)), acc1.z);
            acc1.w = fmaf(m4.z, frcp_approx(fmaf(c5.w, r4.z, 1.f)), acc1.w);

            acc0.x = fmaf(m4.w, frcp_approx(fmaf(c6.x, r4.w, 1.f)), acc0.x);
            acc0.y = fmaf(m4.w, frcp_approx(fmaf(c6.y, r4.w, 1.f)), acc0.y);
            acc0.z = fmaf(m4.w, frcp_approx(fmaf(c6.z, r4.w, 1.f)), acc0.z);
            acc0.w = fmaf(m4.w, frcp_approx(fmaf(c6.w, r4.w, 1.f)), acc0.w);
            acc1.x = fmaf(m4.w, frcp_approx(fmaf(c7.x, r4.w, 1.f)), acc1.x);
            acc1.y = fmaf(m4.w, frcp_approx(fmaf(c7.y, r4.w, 1.f)), acc1.y);
            acc1.z = fmaf(m4.w, frcp_approx(fmaf(c7.z, r4.w, 1.f)), acc1.z);
            acc1.w = fmaf(m4.w, frcp_approx(fmaf(c7.w, r4.w, 1.f)), acc1.w);
        }
    }

    // Reuse sR storage: sp0[1024] | sp1[1024] | st[32][36]
    float* sp0 = &sR[0][0];
    float* sp1 = sp0 + 1024;
    float (*st)[36] = (float(*)[36])(sp1 + 1024);
    __syncthreads();                       // done reading sR
    {
        float* sp = grp ? sp1 : sp0;
        *(float4*)&sp[i * 32 + (t & 3) * 8]     = acc0;
        *(float4*)&sp[i * 32 + (t & 3) * 8 + 4] = acc1;
    }
    __syncthreads();
    {
        const int ii = tid >> 3, j0 = (tid & 7) * 4;
        float4 a  = *(const float4*)&sp0[ii * 32 + j0];
        float4 bb = *(const float4*)&sp1[ii * 32 + j0];
        float4 s  = make_float4(a.x + bb.x + sv, a.y + bb.y + sv,
                                a.z + bb.z + sv, a.w + bb.w + sv);
        *(float4*)&st[ii][j0] = s;
        *(float4*)&g_S[(size_t)(b * SS + I + ii) * SS + J + j0] = s;
    }
    if (ti != tj) {
        __syncthreads();
        const int j = tid >> 3, i0 = (tid & 7) * 4;
        float4 mv = make_float4(-st[i0 + 0][j], -st[i0 + 1][j],
                                -st[i0 + 2][j], -st[i0 + 3][j]);
        *(float4*)&g_S[(size_t)(b * SS + J + j) * SS + I + i0] = mv;
    }
}

// K3: softmax (no-max: |score| <= sum|vm|, overflow-safe) + tiled AV.
// grid = 32 row-tiles x 8 d-tiles. dt==0 blocks also write atten.
__global__ void __launch_bounds__(256) k3_av(const float* __restrict__ V,
                                             float* __restrict__ out_ctx,
                                             float* __restrict__ out_att){
    __shared__ __align__(16) float sA[32][68];
    __shared__ __align__(16) float sV[64][36];
    __shared__ float sRed[32][8];
    __shared__ float sInv[32];

    const int tid = threadIdx.x;
    const int rt  = blockIdx.x >> 3;
    const int dt  = blockIdx.x & 7;
    const int r0  = rt * 32;
    const int b   = r0 >> 9;
    const int jb  = b << 9;
    const int d0  = dt * 32;
    const int i   = tid >> 3;
    const int js  = tid & 7;
    const int dd  = tid & 7;

    // pass 1: sum of exp over the row (each thread a j-comb of 64 elems)
    {
        const float4* S4 = (const float4*)(g_S + (size_t)(r0 + i) * SS);
        float s = 0.f;
        #pragma unroll
        for (int k = 0; k < 16; k++) {
            float4 v = S4[js + k * 8];
            s += __expf(v.x) + __expf(v.y) + __expf(v.z) + __expf(v.w);
        }
        sRed[i][js] = s;
    }
    __syncthreads();
    if (tid < 32) {
        float S = 0.f;
        #pragma unroll
        for (int q = 0; q < 8; q++) S += sRed[tid][q];
        sInv[tid] = 1.f / S;
    }
    __syncthreads();

    const float inv = sInv[i];
    float4 acc = {0,0,0,0};

    for (int jc = 0; jc < 8; jc++) {
        // stage normalized atten chunk (row i, 64 j)
        {
            const float4* S4 = (const float4*)(g_S + (size_t)(r0 + i) * SS + jc * 64 + js * 8);
            float4 v0 = S4[0], v1 = S4[1];
            v0.x = __expf(v0.x) * inv; v0.y = __expf(v0.y) * inv;
            v0.z = __expf(v0.z) * inv; v0.w = __expf(v0.w) * inv;
            v1.x = __expf(v1.x) * inv; v1.y = __expf(v1.y) * inv;
            v1.z = __expf(v1.z) * inv; v1.w = __expf(v1.w) * inv;
            *(float4*)&sA[i][js * 8]     = v0;
            *(float4*)&sA[i][js * 8 + 4] = v1;
            if (dt == 0) {
                float4* O = (float4*)(out_att + (size_t)(r0 + i) * SS + jc * 64 + js * 8);
                O[0] = v0; O[1] = v1;
            }
        }
        // stage V chunk: 64 j-rows x 32 d-cols (8 floats per thread)
        {
            const int jv = tid >> 2, c8 = (tid & 3) * 8;
            const float* Vp = V + (size_t)(jb + jc * 64 + jv) * DD + d0 + c8;
            float4 va = *(const float4*)(Vp);
            float4 vb = *(const float4*)(Vp + 4);
            *(float4*)&sV[jv][c8]     = va;
            *(float4*)&sV[jv][c8 + 4] = vb;
        }
        __syncthreads();
        #pragma unroll 8
        for (int j = 0; j < 64; j++) {
            float a   = sA[i][j];
            float4 v4 = *(const float4*)&sV[j][dd * 4];
            acc.x = fmaf(a, v4.x, acc.x);
            acc.y = fmaf(a, v4.y, acc.y);
            acc.z = fmaf(a, v4.z, acc.z);
            acc.w = fmaf(a, v4.w, acc.w);
        }
        __syncthreads();
    }
    *(float4*)&out_ctx[(size_t)(r0 + i) * DD + d0 + dd * 4] = acc;
}

extern "C" void kernel_launch(void* const* d_in, const int* in_sizes, int n_in,
                              void* d_out, int out_size) {
    (void)in_sizes; (void)n_in; (void)out_size;
    const float* Q  = (const float*)d_in[0];
    const float* V  = (const float*)d_in[2];
    const float* Wm = (const float*)d_in[3];
    const float* vm = (const float*)d_in[4];
    float* out      = (float*)d_out;
    float* out_ctx  = out;              // context [B,S,D]
    float* out_att  = out + BS * DD;    // atten   [B,S,S]

    k0_wt    <<<64, 256>>>(Wm);
    k1_proj  <<<BS / 8, 256>>>(Q);
    k2_scores<<<BB * NP, 256>>>(vm);
    k3_av    <<<(BS / 32) * 8, 256>>>(V, out_ctx, out_att);
}

// round 9
// speedup vs baseline: 1.2505x; 1.2505x over previous
#include <cuda_runtime.h>

#define BB 2
#define SS 512
#define DD 256
#define BS (BB*SS)
#define NT 16            // 512/32 j-tiles per dim
#define NP 136           // NT*(NT+1)/2 triangular tile pairs

// Scratch (allocation-free rule: __device__ globals).
__device__ float g_WT[DD*DD];     // W transposed: [k][e] = W[e][k]
__device__ float g_ET[BB*DD*SS];  // E transposed: [b][e][j] = exp(2*P[b][j][e])
__device__ float g_R [BS*DD];     // R row-major:  [r][e]    = exp(-2*P[r][e])
__device__ float g_S [BS*SS];     // raw scores   [r][j]

__device__ __forceinline__ float frcp_approx(float x){
    float r; asm("rcp.approx.f32 %0, %1;" : "=f"(r) : "f"(x)); return r;
}

// K0: WT[k][e] = W[e][k].  Grid 64 (8x8 tiles of 32x32), block 256 (32x8).
__global__ void __launch_bounds__(256) k0_wt(const float* __restrict__ W){
    __shared__ float t[32][33];
    const int bx = blockIdx.x & 7, by = blockIdx.x >> 3;
    const int lx = threadIdx.x & 31, ly = threadIdx.x >> 5;  // ly 0..7
    #pragma unroll
    for (int r = 0; r < 4; r++)
        t[ly + 8*r][lx] = W[(by*32 + ly + 8*r) * DD + bx*32 + lx];
    __syncthreads();
    #pragma unroll
    for (int r = 0; r < 4; r++)
        g_WT[(bx*32 + ly + 8*r) * DD + by*32 + lx] = t[lx][ly + 8*r];
}

// K1: P = Q @ Wm^T via WT (coalesced L2 reads). i-tile 4, grid 256.
__global__ void __launch_bounds__(256) k1_proj(const float* __restrict__ Q){
    __shared__ __align__(16) float sQT[DD][4];
    const int tid = threadIdx.x;
    const int r0  = blockIdx.x * 4;

    #pragma unroll
    for (int m = 0; m < 4; m++) sQT[tid][m] = Q[(r0 + m) * DD + tid];
    __syncthreads();

    float acc[4] = {0,0,0,0};
    const float* wt = g_WT + tid;
    #pragma unroll 8
    for (int k = 0; k < DD; k++) {
        float wv = __ldg(wt + k * DD);
        float4 q0 = *(const float4*)&sQT[k][0];
        acc[0] = fmaf(wv, q0.x, acc[0]); acc[1] = fmaf(wv, q0.y, acc[1]);
        acc[2] = fmaf(wv, q0.z, acc[2]); acc[3] = fmaf(wv, q0.w, acc[3]);
    }

    const float C2 = 2.885390081777927f; // 2*log2(e)
    const int b  = r0 / SS;
    const int jr = r0 % SS;
    #pragma unroll
    for (int m = 0; m < 4; m++) {
        float p = acc[m];
        g_ET[(size_t)b * DD * SS + (size_t)tid * SS + (jr + m)] = exp2f( C2 * p);
        g_R [(size_t)(r0 + m) * DD + tid]                       = exp2f(-C2 * p);
    }
}

// K2s: scores for one 32x32 tile pair (ti<=tj) via antisymmetry.
__global__ void __launch_bounds__(256) k2_scores(const float* __restrict__ vm){
    __shared__ __align__(16) float sR[32][260];   // R tile; reused after e-loop
    __shared__ float sm2[256];
    __shared__ float s_red[8];

    const int tid  = threadIdx.x;
    const int lane = tid & 31;
    const int w    = tid >> 5;
    const int b    = blockIdx.x / NP;
    int p = blockIdx.x - b * NP;
    int ti = 0;
    while (p >= NT - ti) { p -= NT - ti; ti++; }
    const int tj = ti + p;
    const int I = ti * 32, J = tj * 32;

    {
        float vme = vm[tid];
        sm2[tid] = -2.f * vme;
        float svp = vme;
        #pragma unroll
        for (int off = 16; off; off >>= 1) svp += __shfl_xor_sync(0xffffffffu, svp, off);
        if (lane == 0) s_red[w] = svp;
    }
    {
        const float4* R4 = (const float4*)(g_R + (size_t)(b * SS + I) * DD);
        #pragma unroll
        for (int k = 0; k < 8; k++) {
            int lin = k * 256 + tid;
            int row = lin >> 6;
            int c4  = lin & 63;
            float4 v = R4[row * 64 + c4];
            *(float4*)&sR[row][c4 * 4] = v;
        }
    }
    __syncthreads();
    const float sv = s_red[0] + s_red[1] + s_red[2] + s_red[3] +
                     s_red[4] + s_red[5] + s_red[6] + s_red[7];

    const int grp  = tid >> 7;
    const int t    = tid & 127;
    const int i    = t >> 2;
    const int col0 = tj * 8 + (t & 3) * 2;

    float4 acc0 = {0,0,0,0}, acc1 = {0,0,0,0};
    {
        const float4* EB = (const float4*)(g_ET + (size_t)b * DD * SS);
        const int e0 = grp * 128;
        const float4* pe = EB + (size_t)e0 * (SS/4) + col0;
        float4 n0 = pe[0],   n1 = pe[1];
        float4 n2 = pe[128], n3 = pe[129];
        float4 n4 = pe[256], n5 = pe[257];
        float4 n6 = pe[384], n7 = pe[385];
        pe += 512;

        for (int chunk = 0; chunk < 32; chunk++) {
            float4 c0=n0,c1=n1,c2=n2,c3=n3,c4=n4,c5=n5,c6=n6,c7=n7;
            if (chunk < 31) {
                n0=pe[0];   n1=pe[1];
                n2=pe[128]; n3=pe[129];
                n4=pe[256]; n5=pe[257];
                n6=pe[384]; n7=pe[385];
                pe += 512;
            }
            const int e = e0 + chunk * 4;
            float4 r4 = *(const float4*)&sR[i][e];
            float4 m4 = *(const float4*)&sm2[e];

            acc0.x = fmaf(m4.x, frcp_approx(fmaf(c0.x, r4.x, 1.f)), acc0.x);
            acc0.y = fmaf(m4.x, frcp_approx(fmaf(c0.y, r4.x, 1.f)), acc0.y);
            acc0.z = fmaf(m4.x, frcp_approx(fmaf(c0.z, r4.x, 1.f)), acc0.z);
            acc0.w = fmaf(m4.x, frcp_approx(fmaf(c0.w, r4.x, 1.f)), acc0.w);
            acc1.x = fmaf(m4.x, frcp_approx(fmaf(c1.x, r4.x, 1.f)), acc1.x);
            acc1.y = fmaf(m4.x, frcp_approx(fmaf(c1.y, r4.x, 1.f)), acc1.y);
            acc1.z = fmaf(m4.x, frcp_approx(fmaf(c1.z, r4.x, 1.f)), acc1.z);
            acc1.w = fmaf(m4.x, frcp_approx(fmaf(c1.w, r4.x, 1.f)), acc1.w);

            acc0.x = fmaf(m4.y, frcp_approx(fmaf(c2.x, r4.y, 1.f)), acc0.x);
            acc0.y = fmaf(m4.y, frcp_approx(fmaf(c2.y, r4.y, 1.f)), acc0.y);
            acc0.z = fmaf(m4.y, frcp_approx(fmaf(c2.z, r4.y, 1.f)), acc0.z);
            acc0.w = fmaf(m4.y, frcp_approx(fmaf(c2.w, r4.y, 1.f)), acc0.w);
            acc1.x = fmaf(m4.y, frcp_approx(fmaf(c3.x, r4.y, 1.f)), acc1.x);
            acc1.y = fmaf(m4.y, frcp_approx(fmaf(c3.y, r4.y, 1.f)), acc1.y);
            acc1.z = fmaf(m4.y, frcp_approx(fmaf(c3.z, r4.y, 1.f)), acc1.z);
            acc1.w = fmaf(m4.y, frcp_approx(fmaf(c3.w, r4.y, 1.f)), acc1.w);

            acc0.x = fmaf(m4.z, frcp_approx(fmaf(c4.x, r4.z, 1.f)), acc0.x);
            acc0.y = fmaf(m4.z, frcp_approx(fmaf(c4.y, r4.z, 1.f)), acc0.y);
            acc0.z = fmaf(m4.z, frcp_approx(fmaf(c4.z, r4.z, 1.f)), acc0.z);
            acc0.w = fmaf(m4.z, frcp_approx(fmaf(c4.w, r4.z, 1.f)), acc0.w);
            acc1.x = fmaf(m4.z, frcp_approx(fmaf(c5.x, r4.z, 1.f)), acc1.x);
            acc1.y = fmaf(m4.z, frcp_approx(fmaf(c5.y, r4.z, 1.f)), acc1.y);
            acc1.z = fmaf(m4.z, frcp_approx(fmaf(c5.z, r4.z, 1.f)), acc1.z);
            acc1.w = fmaf(m4.z, frcp_approx(fmaf(c5.w, r4.z, 1.f)), acc1.w);

            acc0.x = fmaf(m4.w, frcp_approx(fmaf(c6.x, r4.w, 1.f)), acc0.x);
            acc0.y = fmaf(m4.w, frcp_approx(fmaf(c6.y, r4.w, 1.f)), acc0.y);
            acc0.z = fmaf(m4.w, frcp_approx(fmaf(c6.z, r4.w, 1.f)), acc0.z);
            acc0.w = fmaf(m4.w, frcp_approx(fmaf(c6.w, r4.w, 1.f)), acc0.w);
            acc1.x = fmaf(m4.w, frcp_approx(fmaf(c7.x, r4.w, 1.f)), acc1.x);
            acc1.y = fmaf(m4.w, frcp_approx(fmaf(c7.y, r4.w, 1.f)), acc1.y);
            acc1.z = fmaf(m4.w, frcp_approx(fmaf(c7.z, r4.w, 1.f)), acc1.z);
            acc1.w = fmaf(m4.w, frcp_approx(fmaf(c7.w, r4.w, 1.f)), acc1.w);
        }
    }

    // Reuse sR storage: sp0[1024] | sp1[1024] | st[32][36]
    float* sp0 = &sR[0][0];
    float* sp1 = sp0 + 1024;
    float (*st)[36] = (float(*)[36])(sp1 + 1024);
    __syncthreads();                       // done reading sR
    {
        float* sp = grp ? sp1 : sp0;
        *(float4*)&sp[i * 32 + (t & 3) * 8]     = acc0;
        *(float4*)&sp[i * 32 + (t & 3) * 8 + 4] = acc1;
    }
    __syncthreads();
    {
        const int ii = tid >> 3, j0 = (tid & 7) * 4;
        float4 a  = *(const float4*)&sp0[ii * 32 + j0];
        float4 bb = *(const float4*)&sp1[ii * 32 + j0];
        float4 s  = make_float4(a.x + bb.x + sv, a.y + bb.y + sv,
                                a.z + bb.z + sv, a.w + bb.w + sv);
        *(float4*)&st[ii][j0] = s;
        *(float4*)&g_S[(size_t)(b * SS + I + ii) * SS + J + j0] = s;
    }
    if (ti != tj) {
        __syncthreads();
        const int j = tid >> 3, i0 = (tid & 7) * 4;
        float4 mv = make_float4(-st[i0 + 0][j], -st[i0 + 1][j],
                                -st[i0 + 2][j], -st[i0 + 3][j]);
        *(float4*)&g_S[(size_t)(b * SS + J + j) * SS + I + i0] = mv;
    }
}

// K3: softmax (no-max, overflow-safe) + AV with 4x register i-tiling and
// 4-way j-split. Thread (jg, ig, d4) accumulates rows {ig+8r} x d-float4.
// grid = 32 row-tiles x 8 d-tiles. dt==0 blocks also write atten.
__global__ void __launch_bounds__(256) k3_av(const float* __restrict__ V,
                                             float* __restrict__ out_ctx,
                                             float* __restrict__ out_att){
    __shared__ __align__(16) float sA[32][68];
    __shared__ __align__(16) float sV[64][36];
    __shared__ float sRed[32][8];
    __shared__ float sInv[32];
    __shared__ __align__(16) float sP[4][64][4];   // jg-partial combine

    const int tid = threadIdx.x;
    const int rt  = blockIdx.x >> 3;
    const int dt  = blockIdx.x & 7;
    const int r0  = rt * 32;
    const int b   = r0 >> 9;
    const int jb  = b << 9;
    const int d0  = dt * 32;
    const int si  = tid >> 3;        // staging row
    const int js  = tid & 7;

    // pass 1: sum of exp over each row
    {
        const float4* S4 = (const float4*)(g_S + (size_t)(r0 + si) * SS);
        float s = 0.f;
        #pragma unroll
        for (int k = 0; k < 16; k++) {
            float4 v = S4[js + k * 8];
            s += __expf(v.x) + __expf(v.y) + __expf(v.z) + __expf(v.w);
        }
        sRed[si][js] = s;
    }
    __syncthreads();
    if (tid < 32) {
        float S = 0.f;
        #pragma unroll
        for (int q = 0; q < 8; q++) S += sRed[tid][q];
        sInv[tid] = 1.f / S;
    }
    __syncthreads();

    const float invs = sInv[si];

    // AV mapping
    const int jg = tid >> 6;         // 0..3  (constant per warp-pair)
    const int s  = tid & 63;
    const int ig = s >> 3;           // 0..7
    const int d4 = s & 7;
    float4 acc[4];
    #pragma unroll
    for (int r = 0; r < 4; r++) acc[r] = make_float4(0,0,0,0);

    for (int jc = 0; jc < 8; jc++) {
        // stage normalized atten chunk (row si, 64 j)
        {
            const float4* S4 = (const float4*)(g_S + (size_t)(r0 + si) * SS + jc * 64 + js * 8);
            float4 v0 = S4[0], v1 = S4[1];
            v0.x = __expf(v0.x) * invs; v0.y = __expf(v0.y) * invs;
            v0.z = __expf(v0.z) * invs; v0.w = __expf(v0.w) * invs;
            v1.x = __expf(v1.x) * invs; v1.y = __expf(v1.y) * invs;
            v1.z = __expf(v1.z) * invs; v1.w = __expf(v1.w) * invs;
            *(float4*)&sA[si][js * 8]     = v0;
            *(float4*)&sA[si][js * 8 + 4] = v1;
            if (dt == 0) {
                float4* O = (float4*)(out_att + (size_t)(r0 + si) * SS + jc * 64 + js * 8);
                O[0] = v0; O[1] = v1;
            }
        }
        // stage V chunk: 64 j-rows x 32 d-cols (8 floats per thread)
        {
            const int jv = tid >> 2, c8 = (tid & 3) * 8;
            const float* Vp = V + (size_t)(jb + jc * 64 + jv) * DD + d0 + c8;
            float4 va = *(const float4*)(Vp);
            float4 vb = *(const float4*)(Vp + 4);
            *(float4*)&sV[jv][c8]     = va;
            *(float4*)&sV[jv][c8 + 4] = vb;
        }
        __syncthreads();
        #pragma unroll 4
        for (int jj = 0; jj < 16; jj++) {
            const int j = jg * 16 + jj;
            float4 v4 = *(const float4*)&sV[j][d4 * 4];
            float a0 = sA[ig     ][j];
            float a1 = sA[ig +  8][j];
            float a2 = sA[ig + 16][j];
            float a3 = sA[ig + 24][j];
            acc[0].x = fmaf(a0, v4.x, acc[0].x); acc[0].y = fmaf(a0, v4.y, acc[0].y);
            acc[0].z = fmaf(a0, v4.z, acc[0].z); acc[0].w = fmaf(a0, v4.w, acc[0].w);
            acc[1].x = fmaf(a1, v4.x, acc[1].x); acc[1].y = fmaf(a1, v4.y, acc[1].y);
            acc[1].z = fmaf(a1, v4.z, acc[1].z); acc[1].w = fmaf(a1, v4.w, acc[1].w);
            acc[2].x = fmaf(a2, v4.x, acc[2].x); acc[2].y = fmaf(a2, v4.y, acc[2].y);
            acc[2].z = fmaf(a2, v4.z, acc[2].z); acc[2].w = fmaf(a2, v4.w, acc[2].w);
            acc[3].x = fmaf(a3, v4.x, acc[3].x); acc[3].y = fmaf(a3, v4.y, acc[3].y);
            acc[3].z = fmaf(a3, v4.z, acc[3].z); acc[3].w = fmaf(a3, v4.w, acc[3].w);
        }
        __syncthreads();
    }

    // combine jg partials, one i-row-group at a time
    #pragma unroll
    for (int r = 0; r < 4; r++) {
        *(float4*)sP[jg][s] = acc[r];
        __syncthreads();
        if (jg == 0) {
            float4 t0 = *(const float4*)sP[0][s];
            float4 t1 = *(const float4*)sP[1][s];
            float4 t2 = *(const float4*)sP[2][s];
            float4 t3 = *(const float4*)sP[3][s];
            float4 o = make_float4(t0.x + t1.x + t2.x + t3.x,
                                   t0.y + t1.y + t2.y + t3.y,
                                   t0.z + t1.z + t2.z + t3.z,
                                   t0.w + t1.w + t2.w + t3.w);
            *(float4*)&out_ctx[(size_t)(r0 + ig + 8 * r) * DD + d0 + d4 * 4] = o;
        }
        __syncthreads();
    }
}

extern "C" void kernel_launch(void* const* d_in, const int* in_sizes, int n_in,
                              void* d_out, int out_size) {
    (void)in_sizes; (void)n_in; (void)out_size;
    const float* Q  = (const float*)d_in[0];
    const float* V  = (const float*)d_in[2];
    const float* Wm = (const float*)d_in[3];
    const float* vm = (const float*)d_in[4];
    float* out      = (float*)d_out;
    float* out_ctx  = out;              // context [B,S,D]
    float* out_att  = out + BS * DD;    // atten   [B,S,S]

    k0_wt    <<<64, 256>>>(Wm);
    k1_proj  <<<BS / 4, 256>>>(Q);
    k2_scores<<<BB * NP, 256>>>(vm);
    k3_av    <<<(BS / 32) * 8, 256>>>(V, out_ctx, out_att);
}

// round 10
// speedup vs baseline: 1.2691x; 1.0149x over previous
#include <cuda_runtime.h>

#define BB 2
#define SS 512
#define DD 256
#define BS (BB*SS)
#define NT 16            // 512/32 j-tiles per dim
#define NP 136           // NT*(NT+1)/2 triangular tile pairs

// Scratch (allocation-free rule: __device__ globals).
__device__ float g_WT[DD*DD];     // W transposed: [k][e] = W[e][k]
__device__ float g_ET[BB*DD*SS];  // E transposed: [b][e][j] = exp(2*P[b][j][e])
__device__ float g_R [BS*DD];     // R row-major:  [r][e]    = exp(-2*P[r][e])
__device__ float g_S [BS*SS];     // EXP scores   [r][j] = exp(sjt[r][j])
__device__ float g_sum[BS];       // softmax denominators per row

__device__ __forceinline__ float frcp_approx(float x){
    float r; asm("rcp.approx.f32 %0, %1;" : "=f"(r) : "f"(x)); return r;
}

// K0: WT[k][e] = W[e][k]; block 0 also zeroes g_sum (for graph replays).
__global__ void __launch_bounds__(256) k0_wt(const float* __restrict__ W){
    __shared__ float t[32][33];
    const int bx = blockIdx.x & 7, by = blockIdx.x >> 3;
    const int lx = threadIdx.x & 31, ly = threadIdx.x >> 5;  // ly 0..7
    if (blockIdx.x == 0) {
        #pragma unroll
        for (int r = threadIdx.x; r < BS; r += 256) g_sum[r] = 0.f;
    }
    #pragma unroll
    for (int r = 0; r < 4; r++)
        t[ly + 8*r][lx] = W[(by*32 + ly + 8*r) * DD + bx*32 + lx];
    __syncthreads();
    #pragma unroll
    for (int r = 0; r < 4; r++)
        g_WT[(bx*32 + ly + 8*r) * DD + by*32 + lx] = t[lx][ly + 8*r];
}

// K1: P = Q @ Wm^T via WT (coalesced L2 reads). i-tile 4, grid 256.
__global__ void __launch_bounds__(256) k1_proj(const float* __restrict__ Q){
    __shared__ __align__(16) float sQT[DD][4];
    const int tid = threadIdx.x;
    const int r0  = blockIdx.x * 4;

    #pragma unroll
    for (int m = 0; m < 4; m++) sQT[tid][m] = Q[(r0 + m) * DD + tid];
    __syncthreads();

    float acc[4] = {0,0,0,0};
    const float* wt = g_WT + tid;
    #pragma unroll 8
    for (int k = 0; k < DD; k++) {
        float wv = __ldg(wt + k * DD);
        float4 q0 = *(const float4*)&sQT[k][0];
        acc[0] = fmaf(wv, q0.x, acc[0]); acc[1] = fmaf(wv, q0.y, acc[1]);
        acc[2] = fmaf(wv, q0.z, acc[2]); acc[3] = fmaf(wv, q0.w, acc[3]);
    }

    const float C2 = 2.885390081777927f; // 2*log2(e)
    const int b  = r0 / SS;
    const int jr = r0 % SS;
    #pragma unroll
    for (int m = 0; m < 4; m++) {
        float p = acc[m];
        g_ET[(size_t)b * DD * SS + (size_t)tid * SS + (jr + m)] = exp2f( C2 * p);
        g_R [(size_t)(r0 + m) * DD + tid]                       = exp2f(-C2 * p);
    }
}

// K2s: EXP-scores for one 32x32 tile pair (ti<=tj) via antisymmetry.
// Direct tile: exp(s). Transposed tile: rcp(exp(s)) = exp(-s).
// Also accumulates softmax row sums into g_sum via atomics.
__global__ void __launch_bounds__(256) k2_scores(const float* __restrict__ vm){
    __shared__ __align__(16) float sR[32][260];   // R tile; reused after e-loop
    __shared__ float sm2[256];
    __shared__ float s_red[8];

    const int tid  = threadIdx.x;
    const int lane = tid & 31;
    const int w    = tid >> 5;
    const int b    = blockIdx.x / NP;
    int p = blockIdx.x - b * NP;
    int ti = 0;
    while (p >= NT - ti) { p -= NT - ti; ti++; }
    const int tj = ti + p;
    const int I = ti * 32, J = tj * 32;

    {
        float vme = vm[tid];
        sm2[tid] = -2.f * vme;
        float svp = vme;
        #pragma unroll
        for (int off = 16; off; off >>= 1) svp += __shfl_xor_sync(0xffffffffu, svp, off);
        if (lane == 0) s_red[w] = svp;
    }
    {
        const float4* R4 = (const float4*)(g_R + (size_t)(b * SS + I) * DD);
        #pragma unroll
        for (int k = 0; k < 8; k++) {
            int lin = k * 256 + tid;
            int row = lin >> 6;
            int c4  = lin & 63;
            float4 v = R4[row * 64 + c4];
            *(float4*)&sR[row][c4 * 4] = v;
        }
    }
    __syncthreads();
    const float sv = s_red[0] + s_red[1] + s_red[2] + s_red[3] +
                     s_red[4] + s_red[5] + s_red[6] + s_red[7];

    const int grp  = tid >> 7;
    const int t    = tid & 127;
    const int i    = t >> 2;
    const int col0 = tj * 8 + (t & 3) * 2;

    float4 acc0 = {0,0,0,0}, acc1 = {0,0,0,0};
    {
        const float4* EB = (const float4*)(g_ET + (size_t)b * DD * SS);
        const int e0 = grp * 128;
        const float4* pe = EB + (size_t)e0 * (SS/4) + col0;
        float4 n0 = pe[0],   n1 = pe[1];
        float4 n2 = pe[128], n3 = pe[129];
        float4 n4 = pe[256], n5 = pe[257];
        float4 n6 = pe[384], n7 = pe[385];
        pe += 512;

        for (int chunk = 0; chunk < 32; chunk++) {
            float4 c0=n0,c1=n1,c2=n2,c3=n3,c4=n4,c5=n5,c6=n6,c7=n7;
            if (chunk < 31) {
                n0=pe[0];   n1=pe[1];
                n2=pe[128]; n3=pe[129];
                n4=pe[256]; n5=pe[257];
                n6=pe[384]; n7=pe[385];
                pe += 512;
            }
            const int e = e0 + chunk * 4;
            float4 r4 = *(const float4*)&sR[i][e];
            float4 m4 = *(const float4*)&sm2[e];

            acc0.x = fmaf(m4.x, frcp_approx(fmaf(c0.x, r4.x, 1.f)), acc0.x);
            acc0.y = fmaf(m4.x, frcp_approx(fmaf(c0.y, r4.x, 1.f)), acc0.y);
            acc0.z = fmaf(m4.x, frcp_approx(fmaf(c0.z, r4.x, 1.f)), acc0.z);
            acc0.w = fmaf(m4.x, frcp_approx(fmaf(c0.w, r4.x, 1.f)), acc0.w);
            acc1.x = fmaf(m4.x, frcp_approx(fmaf(c1.x, r4.x, 1.f)), acc1.x);
            acc1.y = fmaf(m4.x, frcp_approx(fmaf(c1.y, r4.x, 1.f)), acc1.y);
            acc1.z = fmaf(m4.x, frcp_approx(fmaf(c1.z, r4.x, 1.f)), acc1.z);
            acc1.w = fmaf(m4.x, frcp_approx(fmaf(c1.w, r4.x, 1.f)), acc1.w);

            acc0.x = fmaf(m4.y, frcp_approx(fmaf(c2.x, r4.y, 1.f)), acc0.x);
            acc0.y = fmaf(m4.y, frcp_approx(fmaf(c2.y, r4.y, 1.f)), acc0.y);
            acc0.z = fmaf(m4.y, frcp_approx(fmaf(c2.z, r4.y, 1.f)), acc0.z);
            acc0.w = fmaf(m4.y, frcp_approx(fmaf(c2.w, r4.y, 1.f)), acc0.w);
            acc1.x = fmaf(m4.y, frcp_approx(fmaf(c3.x, r4.y, 1.f)), acc1.x);
            acc1.y = fmaf(m4.y, frcp_approx(fmaf(c3.y, r4.y, 1.f)), acc1.y);
            acc1.z = fmaf(m4.y, frcp_approx(fmaf(c3.z, r4.y, 1.f)), acc1.z);
            acc1.w = fmaf(m4.y, frcp_approx(fmaf(c3.w, r4.y, 1.f)), acc1.w);

            acc0.x = fmaf(m4.z, frcp_approx(fmaf(c4.x, r4.z, 1.f)), acc0.x);
            acc0.y = fmaf(m4.z, frcp_approx(fmaf(c4.y, r4.z, 1.f)), acc0.y);
            acc0.z = fmaf(m4.z, frcp_approx(fmaf(c4.z, r4.z, 1.f)), acc0.z);
            acc0.w = fmaf(m4.z, frcp_approx(fmaf(c4.w, r4.z, 1.f)), acc0.w);
            acc1.x = fmaf(m4.z, frcp_approx(fmaf(c5.x, r4.z, 1.f)), acc1.x);
            acc1.y = fmaf(m4.z, frcp_approx(fmaf(c5.y, r4.z, 1.f)), acc1.y);
            acc1.z = fmaf(m4.z, frcp_approx(fmaf(c5.z, r4.z, 1.f)), acc1.z);
            acc1.w = fmaf(m4.z, frcp_approx(fmaf(c5.w, r4.z, 1.f)), acc1.w);

            acc0.x = fmaf(m4.w, frcp_approx(fmaf(c6.x, r4.w, 1.f)), acc0.x);
            acc0.y = fmaf(m4.w, frcp_approx(fmaf(c6.y, r4.w, 1.f)), acc0.y);
            acc0.z = fmaf(m4.w, frcp_approx(fmaf(c6.z, r4.w, 1.f)), acc0.z);
            acc0.w = fmaf(m4.w, frcp_approx(fmaf(c6.w, r4.w, 1.f)), acc0.w);
            acc1.x = fmaf(m4.w, frcp_approx(fmaf(c7.x, r4.w, 1.f)), acc1.x);
            acc1.y = fmaf(m4.w, frcp_approx(fmaf(c7.y, r4.w, 1.f)), acc1.y);
            acc1.z = fmaf(m4.w, frcp_approx(fmaf(c7.z, r4.w, 1.f)), acc1.z);
            acc1.w = fmaf(m4.w, frcp_approx(fmaf(c7.w, r4.w, 1.f)), acc1.w);
        }
    }

    // Reuse sR storage: sp0[1024] | sp1[1024] | st[32][36]
    float* sp0 = &sR[0][0];
    float* sp1 = sp0 + 1024;
    float (*st)[36] = (float(*)[36])(sp1 + 1024);
    __syncthreads();                       // done reading sR
    {
        float* sp = grp ? sp1 : sp0;
        *(float4*)&sp[i * 32 + (t & 3) * 8]     = acc0;
        *(float4*)&sp[i * 32 + (t & 3) * 8 + 4] = acc1;
    }
    __syncthreads();
    {
        const int ii = tid >> 3, j0 = (tid & 7) * 4;
        float4 a  = *(const float4*)&sp0[ii * 32 + j0];
        float4 bb = *(const float4*)&sp1[ii * 32 + j0];
        float4 es;
        es.x = __expf(a.x + bb.x + sv);
        es.y = __expf(a.y + bb.y + sv);
        es.z = __expf(a.z + bb.z + sv);
        es.w = __expf(a.w + bb.w + sv);
        *(float4*)&st[ii][j0] = es;
        *(float4*)&g_S[(size_t)(b * SS + I + ii) * SS + J + j0] = es;
        float rs = es.x + es.y + es.z + es.w;
        rs += __shfl_xor_sync(0xffffffffu, rs, 4);
        rs += __shfl_xor_sync(0xffffffffu, rs, 2);
        rs += __shfl_xor_sync(0xffffffffu, rs, 1);
        if ((tid & 7) == 0) atomicAdd(&g_sum[b * SS + I + ii], rs);
    }
    if (ti != tj) {
        __syncthreads();
        const int j = tid >> 3, i0 = (tid & 7) * 4;
        float4 mv = make_float4(frcp_approx(st[i0 + 0][j]), frcp_approx(st[i0 + 1][j]),
                                frcp_approx(st[i0 + 2][j]), frcp_approx(st[i0 + 3][j]));
        *(float4*)&g_S[(size_t)(b * SS + J + j) * SS + I + i0] = mv;
        float rs = mv.x + mv.y + mv.z + mv.w;
        rs += __shfl_xor_sync(0xffffffffu, rs, 4);
        rs += __shfl_xor_sync(0xffffffffu, rs, 2);
        rs += __shfl_xor_sync(0xffffffffu, rs, 1);
        if ((tid & 7) == 0) atomicAdd(&g_sum[b * SS + J + j], rs);
    }
}

// K3: normalize (inv from g_sum, no exp here) + AV with 4x register i-tiling
// and 4-way j-split. grid = 32 row-tiles x 8 d-tiles. dt==0 writes atten.
__global__ void __launch_bounds__(256) k3_av(const float* __restrict__ V,
                                             float* __restrict__ out_ctx,
                                             float* __restrict__ out_att){
    __shared__ __align__(16) float sA[32][68];
    __shared__ __align__(16) float sV[64][36];
    __shared__ float sInv[32];
    __shared__ __align__(16) float sP[4][64][4];   // jg-partial combine

    const int tid = threadIdx.x;
    const int rt  = blockIdx.x >> 3;
    const int dt  = blockIdx.x & 7;
    const int r0  = rt * 32;
    const int b   = r0 >> 9;
    const int jb  = b << 9;
    const int d0  = dt * 32;
    const int si  = tid >> 3;        // staging row
    const int js  = tid & 7;

    if (tid < 32) sInv[tid] = 1.f / g_sum[r0 + tid];
    __syncthreads();
    const float invs = sInv[si];

    // AV mapping
    const int jg = tid >> 6;         // 0..3
    const int s  = tid & 63;
    const int ig = s >> 3;           // 0..7
    const int d4 = s & 7;
    float4 acc[4];
    #pragma unroll
    for (int r = 0; r < 4; r++) acc[r] = make_float4(0,0,0,0);

    for (int jc = 0; jc < 8; jc++) {
        // stage normalized atten chunk (row si, 64 j) — exp already applied
        {
            const float4* S4 = (const float4*)(g_S + (size_t)(r0 + si) * SS + jc * 64 + js * 8);
            float4 v0 = S4[0], v1 = S4[1];
            v0.x *= invs; v0.y *= invs; v0.z *= invs; v0.w *= invs;
            v1.x *= invs; v1.y *= invs; v1.z *= invs; v1.w *= invs;
            *(float4*)&sA[si][js * 8]     = v0;
            *(float4*)&sA[si][js * 8 + 4] = v1;
            if (dt == 0) {
                float4* O = (float4*)(out_att + (size_t)(r0 + si) * SS + jc * 64 + js * 8);
                O[0] = v0; O[1] = v1;
            }
        }
        // stage V chunk: 64 j-rows x 32 d-cols (8 floats per thread)
        {
            const int jv = tid >> 2, c8 = (tid & 3) * 8;
            const float* Vp = V + (size_t)(jb + jc * 64 + jv) * DD + d0 + c8;
            float4 va = *(const float4*)(Vp);
            float4 vb = *(const float4*)(Vp + 4);
            *(float4*)&sV[jv][c8]     = va;
            *(float4*)&sV[jv][c8 + 4] = vb;
        }
        __syncthreads();
        #pragma unroll 4
        for (int jj = 0; jj < 16; jj++) {
            const int j = jg * 16 + jj;
            float4 v4 = *(const float4*)&sV[j][d4 * 4];
            float a0 = sA[ig     ][j];
            float a1 = sA[ig +  8][j];
            float a2 = sA[ig + 16][j];
            float a3 = sA[ig + 24][j];
            acc[0].x = fmaf(a0, v4.x, acc[0].x); acc[0].y = fmaf(a0, v4.y, acc[0].y);
            acc[0].z = fmaf(a0, v4.z, acc[0].z); acc[0].w = fmaf(a0, v4.w, acc[0].w);
            acc[1].x = fmaf(a1, v4.x, acc[1].x); acc[1].y = fmaf(a1, v4.y, acc[1].y);
            acc[1].z = fmaf(a1, v4.z, acc[1].z); acc[1].w = fmaf(a1, v4.w, acc[1].w);
            acc[2].x = fmaf(a2, v4.x, acc[2].x); acc[2].y = fmaf(a2, v4.y, acc[2].y);
            acc[2].z = fmaf(a2, v4.z, acc[2].z); acc[2].w = fmaf(a2, v4.w, acc[2].w);
            acc[3].x = fmaf(a3, v4.x, acc[3].x); acc[3].y = fmaf(a3, v4.y, acc[3].y);
            acc[3].z = fmaf(a3, v4.z, acc[3].z); acc[3].w = fmaf(a3, v4.w, acc[3].w);
        }
        __syncthreads();
    }

    // combine jg partials, one i-row-group at a time
    #pragma unroll
    for (int r = 0; r < 4; r++) {
        *(float4*)sP[jg][s] = acc[r];
        __syncthreads();
        if (jg == 0) {
            float4 t0 = *(const float4*)sP[0][s];
            float4 t1 = *(const float4*)sP[1][s];
            float4 t2 = *(const float4*)sP[2][s];
            float4 t3 = *(const float4*)sP[3][s];
            float4 o = make_float4(t0.x + t1.x + t2.x + t3.x,
                                   t0.y + t1.y + t2.y + t3.y,
                                   t0.z + t1.z + t2.z + t3.z,
                                   t0.w + t1.w + t2.w + t3.w);
            *(float4*)&out_ctx[(size_t)(r0 + ig + 8 * r) * DD + d0 + d4 * 4] = o;
        }
        __syncthreads();
    }
}

extern "C" void kernel_launch(void* const* d_in, const int* in_sizes, int n_in,
                              void* d_out, int out_size) {
    (void)in_sizes; (void)n_in; (void)out_size;
    const float* Q  = (const float*)d_in[0];
    const float* V  = (const float*)d_in[2];
    const float* Wm = (const float*)d_in[3];
    const float* vm = (const float*)d_in[4];
    float* out      = (float*)d_out;
    float* out_ctx  = out;              // context [B,S,D]
    float* out_att  = out + BS * DD;    // atten   [B,S,S]

    k0_wt    <<<64, 256>>>(Wm);
    k1_proj  <<<BS / 4, 256>>>(Q);
    k2_scores<<<BB * NP, 256>>>(vm);
    k3_av    <<<(BS / 32) * 8, 256>>>(V, out_ctx, out_att);
}